// round 4
// baseline (speedup 1.0000x reference)
#include <cuda_runtime.h>

// DynamicPatching: B=32, C=64, T=8192, S=64.
// out[b][s][c][p] = (p < len_bs) ? tensor[b][c][start_bs + p] : 0
// Output (B, S, C, max_len) row-major.
// Both sides vectorized: LDG.128 aligned-pair + shift-select for the misaligned
// source, STG.128 with per-row alignment fixup. Pad region = store-only.

#define PB 32
#define PC 64
#define PT 8192
#define PS 64

__device__ __forceinline__ float4 shift_sel(float4 lo, float4 hi, int a)
{
    float4 v;
    switch (a) {
        case 0:  v = lo; break;
        case 1:  v.x = lo.y; v.y = lo.z; v.z = lo.w; v.w = hi.x; break;
        case 2:  v.x = lo.z; v.y = lo.w; v.z = hi.x; v.w = hi.y; break;
        default: v.x = lo.w; v.y = hi.x; v.z = hi.y; v.w = hi.z; break;
    }
    return v;
}

__global__ void __launch_bounds__(256)
dynamic_patching_kernel(const float* __restrict__ tensor,
                        const int*   __restrict__ cps,   // (B, S+1) int32
                        float*       __restrict__ out,
                        int max_len)
{
    // 2 blocks per (b,s): each block covers 32 of the 64 channels.
    const int bs   = blockIdx.x >> 1;
    const int half = blockIdx.x & 1;
    const int b    = bs >> 6;            // / PS
    const int s    = bs & (PS - 1);      // % PS

    const int start = __ldg(cps + b * (PS + 1) + s);
    const int len   = __ldg(cps + b * (PS + 1) + s + 1) - start;

    const float* __restrict__ row0 = tensor + ((size_t)b * PC) * PT + start;
    const long long out_base = (long long)bs * PC * (long long)max_len;

    const int wid  = threadIdx.x >> 5;   // 0..7
    const int lane = threadIdx.x & 31;

    #pragma unroll
    for (int r = 0; r < 4; ++r) {
        const int c = half * 32 + wid * 4 + r;
        const float* __restrict__ src = row0 + (size_t)c * PT;  // element 'start'
        const long long row_idx = out_base + (long long)c * (long long)max_len;
        float* __restrict__ dst = out + row_idx;

        // First 16B-aligned output offset in this row.
        const int p0 = (int)((4 - (row_idx & 3)) & 3);
        const int nv = (max_len - p0) >> 2;          // # float4 chunks
        const int ts = p0 + (nv << 2);               // scalar tail start

        // Scalar head (< p0) and tail (< 4), one lane each.
        if (lane < p0)
            dst[lane] = (lane < len) ? __ldg(src + lane) : 0.0f;
        {
            const int p = ts + lane;
            if (p < max_len)
                dst[p] = (p < len) ? __ldg(src + p) : 0.0f;
        }

        // Region split for the vector body (chunk k -> p = p0 + 4k):
        //   k <  kfull : all 4 elements valid  -> aligned LDG.128 pair + select
        //   k >= kzero : all 4 elements padded -> zero STG.128, no loads
        //   in between : single boundary chunk -> predicated scalar loads
        const int lp    = len - p0;
        const int kfull = (lp > 0) ? (lp >> 2) : 0;
        const int kzero = (lp > 0) ? ((lp + 3) >> 2) : 0;

        // Aligned source base for the vector region. src+p0 is element
        // q = start+p0; a = q & 3; base (q - a) is 16B-aligned and >= row start.
        const int a = (int)(((size_t)(src + p0)) >> 2) & 3;
        const float4* __restrict__ ab =
            reinterpret_cast<const float4*>(src + p0 - a);

        for (int k = lane; k < nv; k += 32) {
            const int p = p0 + (k << 2);
            float4 v;
            if (k < kfull) {
                const float4 lo = __ldg(ab + k);
                const float4 hi = a ? __ldg(ab + k + 1) : lo;
                v = shift_sel(lo, hi, a);
            } else if (k >= kzero) {
                v = make_float4(0.0f, 0.0f, 0.0f, 0.0f);
            } else {
                v.x = (p + 0 < len) ? __ldg(src + p + 0) : 0.0f;
                v.y = (p + 1 < len) ? __ldg(src + p + 1) : 0.0f;
                v.z = (p + 2 < len) ? __ldg(src + p + 2) : 0.0f;
                v.w = (p + 3 < len) ? __ldg(src + p + 3) : 0.0f;
            }
            *reinterpret_cast<float4*>(dst + p) = v;
        }
    }
}

extern "C" void kernel_launch(void* const* d_in, const int* in_sizes, int n_in,
                              void* d_out, int out_size)
{
    const float* tensor = (const float*)d_in[0];
    const int*   cps    = (const int*)d_in[1];
    float*       out    = (float*)d_out;

    const int max_len = out_size / (PB * PS * PC);

    dynamic_patching_kernel<<<PB * PS * 2, 256>>>(tensor, cps, out, max_len);
}

// round 5
// speedup vs baseline: 1.1080x; 1.1080x over previous
#include <cuda_runtime.h>

// DynamicPatching: B=32, C=64, T=8192, S=64.
// out[b][s][c][p] = (p < len_bs) ? tensor[b][c][start_bs + p] : 0
// Output (B, S, C, max_len) row-major.
// R2 structure (predicated scalar loads, STG.128 body) + two-phase software
// pipeline: batch all 16 loads across 4 rows before the 4 stores (MLP ~16),
// heads/tails hoisted out of the hot loop, streaming cache hints (no reuse).

#define PB 32
#define PC 64
#define PT 8192
#define PS 64

__device__ __forceinline__ float ldcs(const float* p) {
    float v;
    asm volatile("ld.global.cs.f32 %0, [%1];" : "=f"(v) : "l"(p));
    return v;
}
__device__ __forceinline__ void stcs4(float* p, float4 v) {
    asm volatile("st.global.cs.v4.f32 [%0], {%1,%2,%3,%4};"
                 :: "l"(p), "f"(v.x), "f"(v.y), "f"(v.z), "f"(v.w) : "memory");
}

__global__ void __launch_bounds__(256)
dynamic_patching_kernel(const float* __restrict__ tensor,
                        const int*   __restrict__ cps,   // (B, S+1) int32
                        float*       __restrict__ out,
                        int max_len)
{
    // 2 blocks per (b,s): each block covers 32 of the 64 channels.
    const int bs   = blockIdx.x >> 1;
    const int half = blockIdx.x & 1;
    const int b    = bs >> 6;            // / PS
    const int s    = bs & (PS - 1);      // % PS

    const int start = __ldg(cps + b * (PS + 1) + s);
    const int len   = __ldg(cps + b * (PS + 1) + s + 1) - start;

    const float* __restrict__ row0 = tensor + ((size_t)b * PC) * PT + start;
    const long long out_base = (long long)bs * PC * (long long)max_len;

    const int wid  = threadIdx.x >> 5;   // 0..7
    const int lane = threadIdx.x & 31;

    const int cbase = half * 32 + wid * 4;

    // Per-row invariants (unrolled -> registers).
    const float* src[4];
    float*       dst[4];
    int p0[4], nv[4];
    int nvmax = 0;

    #pragma unroll
    for (int r = 0; r < 4; ++r) {
        const int c = cbase + r;
        src[r] = row0 + (size_t)c * PT;
        const long long row_idx = out_base + (long long)c * (long long)max_len;
        dst[r] = out + row_idx;
        p0[r]  = (int)((4 - (row_idx & 3)) & 3);
        nv[r]  = (max_len - p0[r]) >> 2;
        nvmax  = max(nvmax, nv[r]);
    }

    // Heads (< p0) and tails (< 4 elems), hoisted out of the hot loop.
    #pragma unroll
    for (int r = 0; r < 4; ++r) {
        if (lane < p0[r])
            dst[r][lane] = (lane < len) ? ldcs(src[r] + lane) : 0.0f;
        const int p = p0[r] + (nv[r] << 2) + lane;
        if (p < max_len)
            dst[r][p] = (p < len) ? ldcs(src[r] + p) : 0.0f;
    }

    // Vector body: two-phase per k-step. Phase 1: 16 predicated loads across
    // all 4 rows (independent, all in flight). Phase 2: 4 STG.128.
    for (int kb = 0; kb < nvmax; kb += 32) {
        const int k = kb + lane;
        float4 v[4];

        #pragma unroll
        for (int r = 0; r < 4; ++r) {
            const int p = p0[r] + (k << 2);
            v[r] = make_float4(0.0f, 0.0f, 0.0f, 0.0f);
            if (k < nv[r]) {
                if (p + 0 < len) v[r].x = ldcs(src[r] + p + 0);
                if (p + 1 < len) v[r].y = ldcs(src[r] + p + 1);
                if (p + 2 < len) v[r].z = ldcs(src[r] + p + 2);
                if (p + 3 < len) v[r].w = ldcs(src[r] + p + 3);
            }
        }

        #pragma unroll
        for (int r = 0; r < 4; ++r) {
            if (k < nv[r])
                stcs4(dst[r] + p0[r] + (k << 2), v[r]);
        }
    }
}

extern "C" void kernel_launch(void* const* d_in, const int* in_sizes, int n_in,
                              void* d_out, int out_size)
{
    const float* tensor = (const float*)d_in[0];
    const int*   cps    = (const int*)d_in[1];
    float*       out    = (float*)d_out;

    const int max_len = out_size / (PB * PS * PC);

    dynamic_patching_kernel<<<PB * PS * 2, 256>>>(tensor, cps, out, max_len);
}